// round 15
// baseline (speedup 1.0000x reference)
#include <cuda_runtime.h>
#include <cuda_bf16.h>
#include <math.h>
#include <stdint.h>

// Problem constants
#define NN   4096
#define PP   128
#define QQ   128
#define HD   256
#define KH   8
#define DD   64
#define SEG  64
#define NSEG 64
#define NS   2048            // sublist length (2 sublists per head)
#define TBL  2049            // per-sublist table entries

// ======================= helpers =============================
__device__ __forceinline__ uint32_t smem_u32(const void* p) {
    uint32_t a;
    asm("{ .reg .u64 t; cvta.to.shared.u64 t, %1; cvt.u32.u64 %0, t; }" : "=r"(a) : "l"(p));
    return a;
}
__device__ __forceinline__ void cp16(uint32_t saddr, const void* g) {
    asm volatile("cp.async.cg.shared.global [%0], [%1], 16;" :: "r"(saddr), "l"(g) : "memory");
}
#define CP_COMMIT() asm volatile("cp.async.commit_group;" ::: "memory")
#define CP_WAIT(n)  asm volatile("cp.async.wait_group %0;" :: "n"(n) : "memory")

__device__ __forceinline__ void ldsm4(uint32_t* r, uint32_t addr) {
    asm volatile("ldmatrix.sync.aligned.m8n8.x4.shared.b16 {%0,%1,%2,%3}, [%4];"
        : "=r"(r[0]), "=r"(r[1]), "=r"(r[2]), "=r"(r[3]) : "r"(addr));
}
__device__ __forceinline__ void mma_bf16(float* c, const uint32_t* a, const uint32_t* b) {
    asm volatile("mma.sync.aligned.m16n8k16.row.col.f32.bf16.bf16.f32 "
        "{%0,%1,%2,%3}, {%4,%5,%6,%7}, {%8,%9}, {%0,%1,%2,%3};"
        : "+f"(c[0]), "+f"(c[1]), "+f"(c[2]), "+f"(c[3])
        : "r"(a[0]), "r"(a[1]), "r"(a[2]), "r"(a[3]), "r"(b[0]), "r"(b[1]));
}
__device__ __forceinline__ uint32_t pack2(__nv_bfloat16 a, __nv_bfloat16 b) {
    return (uint32_t)__bfloat16_as_ushort(a) | ((uint32_t)__bfloat16_as_ushort(b) << 16);
}

// ---------------- device scratch ----------------
__device__ __nv_bfloat16 g_Whi[HD * PP * QQ];    // [h][q][p] transposed, hi part
__device__ __nv_bfloat16 g_Wlo[HD * PP * QQ];    // lo part
__device__ float g_x[NN * HD];
__device__ float g_xt[KH * NN * DD];
__device__ float g_ssrc[KH * NN];
__device__ float g_sdst[KH * NN];
__device__ float g_bsorted[KH * NN];
__device__ int   g_sigma[KH * NN];
__device__ float g_e1[KH * NN];
__device__ float g_e2[KH * NN];
__device__ float g_bmax[KH];
__device__ unsigned int g_bmaxu[KH];
__device__ float g_segP[KH * NSEG * DD];
__device__ float g_segS[KH * NSEG * DD];
__device__ float g_segPs[KH * NSEG];
__device__ float g_segSs[KH * NSEG];
__device__ float g_P2x[KH * 2 * TBL * DD];       // per-sublist prefix of e2*xt
__device__ float g_S1x[KH * 2 * TBL * DD];       // per-sublist suffix of e1*xt
__device__ float g_P2s[KH * 2 * TBL];
__device__ float g_S1s[KH * 2 * TBL];

// ============================================================================
// K0: split W into bf16 hi/lo, transposed to [h][q][p]. Also zero g_bmaxu.
// ============================================================================
__global__ __launch_bounds__(256) void k_wsplit(const float* __restrict__ W)
{
    extern __shared__ float ws[];   // [128][130] fp32
    const int h = blockIdx.x;
    const int tid = threadIdx.x;

    if (blockIdx.x == 0 && tid < KH) g_bmaxu[tid] = 0u;

    for (int e = tid; e < PP * QQ; e += 256) {
        int p = e >> 7, q = e & 127;
        ws[p * 130 + q] = W[(size_t)h * PP * QQ + e];
    }
    __syncthreads();

    uint4* dhi = (uint4*)(g_Whi + (size_t)h * PP * QQ);
    uint4* dlo = (uint4*)(g_Wlo + (size_t)h * PP * QQ);
#pragma unroll
    for (int i = 0; i < 8; i++) {
        int o8 = tid + i * 256;
        int q  = o8 >> 4;
        int p0 = (o8 & 15) * 8;
        unsigned short hs[8], ls[8];
#pragma unroll
        for (int j = 0; j < 8; j++) {
            float x = ws[(p0 + j) * 130 + q];
            __nv_bfloat16 hb = __float2bfloat16(x);
            __nv_bfloat16 lb = __float2bfloat16(x - __bfloat162float(hb));
            hs[j] = __bfloat16_as_ushort(hb);
            ls[j] = __bfloat16_as_ushort(lb);
        }
        uint4 vh, vl;
        vh.x = hs[0] | ((uint32_t)hs[1] << 16); vh.y = hs[2] | ((uint32_t)hs[3] << 16);
        vh.z = hs[4] | ((uint32_t)hs[5] << 16); vh.w = hs[6] | ((uint32_t)hs[7] << 16);
        vl.x = ls[0] | ((uint32_t)ls[1] << 16); vl.y = ls[2] | ((uint32_t)ls[3] << 16);
        vl.z = ls[4] | ((uint32_t)ls[5] << 16); vl.w = ls[6] | ((uint32_t)ls[7] << 16);
        dhi[o8] = vh;
        dlo[o8] = vl;
    }
}

// ============================================================================
// K1: bilinear via HMMA (frozen R9 config). 261us proven.
// ============================================================================
#define ASTRIDE 272
#define A_HI    0
#define A_LO    34816
#define B_BASE  69632
#define B_STAGE 69632
#define B_LO_OFF 34816
#define SM_RED  208896
#define BIL_SMEM (208896 + 8192)

__device__ __forceinline__ void prefB(uint32_t dstbase, int h, int tid)
{
    const char* shi = (const char*)g_Whi + (size_t)h * 32768;
    const char* slo = (const char*)g_Wlo + (size_t)h * 32768;
#pragma unroll
    for (int i = 0; i < 8; i++) {
        int c = tid + i * 256;
        uint32_t d = dstbase + (uint32_t)(c >> 4) * ASTRIDE + (uint32_t)(c & 15) * 16;
        cp16(d, shi + (size_t)c * 16);
        cp16(d + B_LO_OFF, slo + (size_t)c * 16);
    }
}

__global__ __launch_bounds__(256, 1)
void k_bil_hmma(const float* __restrict__ prices,
                const float* __restrict__ news,
                const float* __restrict__ bias)
{
    extern __shared__ char sm[];
    const uint32_t sb = smem_u32(sm);
    float* red = (float*)(sm + SM_RED);     // [2][128][8]
    const int tid  = threadIdx.x;
    const int wid  = tid >> 5;
    const int lane = tid & 31;
    const int n0   = blockIdx.x * 128;
    const int h0   = blockIdx.y * 8;
    const int g = lane >> 2, ctg = lane & 3;
    const int wm = wid & 3;
    const int ch = wid >> 2;

    prefB(sb + B_BASE, h0, tid);
    CP_COMMIT();

#pragma unroll
    for (int i = 0; i < 16; i++) {
        int e4  = tid + i * 256;
        int row = e4 >> 5;
        int c4  = e4 & 31;
        float4 v = *(const float4*)&prices[(size_t)(n0 + row) * PP + c4 * 4];
        __nv_bfloat16 hx = __float2bfloat16(v.x), hy = __float2bfloat16(v.y);
        __nv_bfloat16 hz = __float2bfloat16(v.z), hw = __float2bfloat16(v.w);
        uint2 vh, vl;
        vh.x = pack2(hx, hy); vh.y = pack2(hz, hw);
        vl.x = pack2(__float2bfloat16(v.x - __bfloat162float(hx)),
                     __float2bfloat16(v.y - __bfloat162float(hy)));
        vl.y = pack2(__float2bfloat16(v.z - __bfloat162float(hz)),
                     __float2bfloat16(v.w - __bfloat162float(hw)));
        uint32_t off = (uint32_t)row * ASTRIDE + (uint32_t)c4 * 8;
        *(uint2*)(sm + A_HI + off) = vh;
        *(uint2*)(sm + A_LO + off) = vl;
    }

    const uint32_t arow = (uint32_t)(lane & 15);
    const uint32_t akb  = (uint32_t)(lane >> 4) * 16;
    const uint32_t ahi0 = sb + A_HI + (wm * 32 + arow) * ASTRIDE + akb;
    const uint32_t alo0 = ahi0 + (A_LO - A_HI);
    const uint32_t brow = (uint32_t)((lane & 7) + ((lane >> 4) << 3));
    const uint32_t bkb  = (uint32_t)((lane >> 3) & 1) * 16;
    const uint32_t boff = (ch * 64 + brow) * ASTRIDE + bkb;

#pragma unroll 1
    for (int hh = 0; hh < 8; hh++) {
        CP_WAIT(0);
        __syncthreads();

        if (hh > 0 && tid < 128) {
            const float* rr = red + ((hh - 1) & 1) * 1024 + tid * 8;
            float s = ((rr[0] + rr[1]) + (rr[2] + rr[3]))
                    + ((rr[4] + rr[5]) + (rr[6] + rr[7]));
            g_x[(size_t)(n0 + tid) * HD + (h0 + hh - 1)] = s + bias[h0 + hh - 1];
        }
        if (hh < 7) { prefB(sb + B_BASE + ((hh + 1) & 1) * B_STAGE, h0 + hh + 1, tid); CP_COMMIT(); }

        float acc[2][4][2][4];
#pragma unroll
        for (int mt = 0; mt < 2; mt++)
#pragma unroll
            for (int nb = 0; nb < 4; nb++)
#pragma unroll
                for (int t = 0; t < 2; t++)
#pragma unroll
                    for (int c = 0; c < 4; c++) acc[mt][nb][t][c] = 0.f;

        const uint32_t bb = sb + B_BASE + (uint32_t)(hh & 1) * B_STAGE + boff;

#pragma unroll
        for (int ks = 0; ks < 8; ks++) {
            uint32_t ah[2][4], al[2][4];
            ldsm4(ah[0], ahi0 + ks * 32);
            ldsm4(ah[1], ahi0 + 16 * ASTRIDE + ks * 32);
            ldsm4(al[0], alo0 + ks * 32);
            ldsm4(al[1], alo0 + 16 * ASTRIDE + ks * 32);
            uint32_t bh[4][4], bl[4][4];
#pragma unroll
            for (int nb = 0; nb < 4; nb++) {
                ldsm4(bh[nb], bb + (uint32_t)nb * (16 * ASTRIDE) + ks * 32);
                ldsm4(bl[nb], bb + B_LO_OFF + (uint32_t)nb * (16 * ASTRIDE) + ks * 32);
            }
#pragma unroll
            for (int nb = 0; nb < 4; nb++)
#pragma unroll
                for (int mt = 0; mt < 2; mt++) {
                    mma_bf16(acc[mt][nb][0], ah[mt], bh[nb] + 0);
                    mma_bf16(acc[mt][nb][1], ah[mt], bh[nb] + 2);
                }
#pragma unroll
            for (int nb = 0; nb < 4; nb++)
#pragma unroll
                for (int mt = 0; mt < 2; mt++) {
                    mma_bf16(acc[mt][nb][0], ah[mt], bl[nb] + 0);
                    mma_bf16(acc[mt][nb][1], ah[mt], bl[nb] + 2);
                }
#pragma unroll
            for (int nb = 0; nb < 4; nb++)
#pragma unroll
                for (int mt = 0; mt < 2; mt++) {
                    mma_bf16(acc[mt][nb][0], al[mt], bh[nb] + 0);
                    mma_bf16(acc[mt][nb][1], al[mt], bh[nb] + 2);
                }
        }

        float* redw = red + (hh & 1) * 1024;
#pragma unroll
        for (int mt = 0; mt < 2; mt++) {
            const int r0 = n0 + wm * 32 + mt * 16 + g;
            const int r1 = r0 + 8;
            float2 nv0[8], nv1[8];
#pragma unroll
            for (int i = 0; i < 8; i++) {
                int col = ch * 64 + (i >> 1) * 16 + (i & 1) * 8 + ctg * 2;
                nv0[i] = *(const float2*)&news[(size_t)r0 * QQ + col];
                nv1[i] = *(const float2*)&news[(size_t)r1 * QQ + col];
            }
            float xp0 = 0.f, xp1 = 0.f;
#pragma unroll
            for (int i = 0; i < 8; i++) {
                int nb = i >> 1, t = i & 1;
                xp0 += acc[mt][nb][t][0] * nv0[i].x + acc[mt][nb][t][1] * nv0[i].y;
                xp1 += acc[mt][nb][t][2] * nv1[i].x + acc[mt][nb][t][3] * nv1[i].y;
            }
            redw[(wm * 32 + mt * 16 + g) * 8 + ch * 4 + ctg]     = xp0;
            redw[(wm * 32 + mt * 16 + g + 8) * 8 + ch * 4 + ctg] = xp1;
        }
    }

    __syncthreads();
    if (tid < 128) {
        const float* rr = red + 1 * 1024 + tid * 8;
        float s = ((rr[0] + rr[1]) + (rr[2] + rr[3]))
                + ((rr[4] + rr[5]) + (rr[6] + rr[7]));
        g_x[(size_t)(n0 + tid) * HD + (h0 + 7)] = s + bias[h0 + 7];
    }
}

// ============================================================================
// K2: xt = x @ Wt^T -> g_xt; fused s_src/s_dst + per-head bmax (atomicMax).
// ============================================================================
__global__ __launch_bounds__(256, 2)
void k_xt(const float* __restrict__ Wt, const float* __restrict__ avec)
{
    const int n0 = blockIdx.x * 128;
    const int j0 = blockIdx.y * 128;
    const int tid = threadIdx.x;
    const int tx = tid & 15;
    const int ty = tid >> 4;

    __shared__ float As[16][128];
    __shared__ float Bs[16][128];
    __shared__ float sredS[2][128][8];
    __shared__ float sredD[2][128][8];

    float acc[8][8];
#pragma unroll
    for (int i = 0; i < 8; i++)
#pragma unroll
        for (int j = 0; j < 8; j++) acc[i][j] = 0.f;

    for (int h0 = 0; h0 < HD; h0 += 16) {
#pragma unroll
        for (int l = 0; l < 2; l++) {
            int f = tid + l * 256;
            int n = f >> 2;
            int hv = (f & 3) * 4;
            float4 v = *(const float4*)&g_x[(size_t)(n0 + n) * HD + h0 + hv];
            As[hv + 0][n] = v.x; As[hv + 1][n] = v.y;
            As[hv + 2][n] = v.z; As[hv + 3][n] = v.w;
        }
#pragma unroll
        for (int l = 0; l < 2; l++) {
            int f = tid + l * 256;
            int j = f >> 2;
            int hv = (f & 3) * 4;
            float4 v = *(const float4*)&Wt[(size_t)(j0 + j) * HD + h0 + hv];
            Bs[hv + 0][j] = v.x; Bs[hv + 1][j] = v.y;
            Bs[hv + 2][j] = v.z; Bs[hv + 3][j] = v.w;
        }
        __syncthreads();
#pragma unroll
        for (int kk = 0; kk < 16; kk++) {
            float a[8], b[8];
            *(float4*)&a[0] = *(const float4*)&As[kk][ty * 8];
            *(float4*)&a[4] = *(const float4*)&As[kk][ty * 8 + 4];
            *(float4*)&b[0] = *(const float4*)&Bs[kk][tx * 8];
            *(float4*)&b[4] = *(const float4*)&Bs[kk][tx * 8 + 4];
#pragma unroll
            for (int i = 0; i < 8; i++)
#pragma unroll
                for (int j = 0; j < 8; j++) acc[i][j] += a[i] * b[j];
        }
        __syncthreads();
    }

#pragma unroll
    for (int i = 0; i < 8; i++) {
        int n = n0 + ty * 8 + i;
#pragma unroll
        for (int jj = 0; jj < 8; jj++) {
            int j = j0 + tx * 8 + jj;
            int k = j >> 6, d = j & 63;
            g_xt[((size_t)k * NN + n) * DD + d] = acc[i][jj];
        }
    }

    // fused scores
    {
        const int khalf = tx >> 3;
        const int kk = (j0 >> 6) + khalf;
        const float* av = avec + kk * 128 + (tx & 7) * 8;
        float asv[8], adv[8];
#pragma unroll
        for (int jj = 0; jj < 8; jj++) { asv[jj] = av[jj]; adv[jj] = av[64 + jj]; }
#pragma unroll
        for (int i = 0; i < 8; i++) {
            float ps = 0.f, pd = 0.f;
#pragma unroll
            for (int jj = 0; jj < 8; jj++) {
                ps += acc[i][jj] * asv[jj];
                pd += acc[i][jj] * adv[jj];
            }
            sredS[khalf][ty * 8 + i][tx & 7] = ps;
            sredD[khalf][ty * 8 + i][tx & 7] = pd;
        }
    }
    __syncthreads();
    {
        const int khalf = tid >> 7;
        const int n = tid & 127;
        const int kk = (j0 >> 6) + khalf;
        const float* rs = sredS[khalf][n];
        const float* rd = sredD[khalf][n];
        float ss = ((rs[0] + rs[1]) + (rs[2] + rs[3])) + ((rs[4] + rs[5]) + (rs[6] + rs[7]));
        float sd = ((rd[0] + rd[1]) + (rd[2] + rd[3])) + ((rd[4] + rd[5]) + (rd[6] + rd[7]));
        g_ssrc[kk * NN + n0 + n] = ss;
        g_sdst[kk * NN + n0 + n] = sd;
        uint32_t u = __float_as_uint(sd);
        uint32_t enc = (u & 0x80000000u) ? ~u : (u | 0x80000000u);
        atomicMax(&g_bmaxu[kk], enc);
    }
}

// ============================================================================
// K3a: bitonic sort of independent 2048-sublists. grid (2, KH), 1024 threads.
// u32 keys (top-20 monotone bits | 12-bit local idx). bmax from g_bmaxu.
// ============================================================================
__global__ __launch_bounds__(1024)
void k_sort()
{
    const int sub = blockIdx.x;
    const int k = blockIdx.y;
    const int base = k * NN + sub * NS;
    __shared__ uint32_t v[NS];   // 8KB

    for (int i = threadIdx.x; i < NS; i += 1024) {
        uint32_t u = __float_as_uint(g_sdst[base + i]);
        uint32_t key = (u & 0x80000000u) ? ~u : (u | 0x80000000u);
        v[i] = (key & 0xFFFFF000u) | (uint32_t)i;
    }

    int prev = 64;
    for (int size = 2; size <= NS; size <<= 1) {
        for (int stride = size >> 1; stride > 0; stride >>= 1) {
            if (prev > 32 || stride > 32) __syncthreads(); else __syncwarp();
            int t = threadIdx.x;                 // exactly NS/2 = 1024 pairs
            int i = (t << 1) - (t & (stride - 1));
            int j = i + stride;
            bool up = ((i & size) == 0);
            uint32_t a = v[i], b = v[j];
            if ((a > b) == up) { v[i] = b; v[j] = a; }
            prev = stride;
        }
    }
    __syncthreads();

    uint32_t e = g_bmaxu[k];
    uint32_t um = (e & 0x80000000u) ? (e ^ 0x80000000u) : ~e;
    const float bmax = __uint_as_float(um);

    for (int i = threadIdx.x; i < NS; i += 1024) {
        int idx = (int)(v[i] & 0xFFFu);          // local index within sublist
        float val = g_sdst[base + idx];
        g_bsorted[base + i] = val;
        g_sigma[base + i]   = sub * NS + idx;    // global n index
        float b = val - bmax;
        g_e1[base + i] = expf(b);
        g_e2[base + i] = expf(0.2f * b);
    }
    if (threadIdx.x == 0 && sub == 0) g_bmax[k] = bmax;
}

// ============================================================================
// K3b: per-segment sums (unchanged; segments never cross sublist boundaries)
// ============================================================================
__global__ __launch_bounds__(256) void k_segsum()
{
    const int seg = blockIdx.x, k = blockIdx.y;
    const int tid = threadIdx.x;
    const int i4 = tid >> 6, d = tid & 63;

    __shared__ float e1s[64], e2s[64];
    __shared__ int   sigs[64];
    __shared__ float pP[4][64], pS[4][64];

    if (tid < 64) {
        int m = seg * SEG + tid;
        e1s[tid] = g_e1[k * NN + m];
        e2s[tid] = g_e2[k * NN + m];
        sigs[tid] = g_sigma[k * NN + m];
    }
    __syncthreads();

    float sp = 0.f, ss = 0.f;
#pragma unroll
    for (int it = 0; it < 16; it++) {
        int i = it * 4 + i4;
        float val = g_xt[((size_t)k * NN + sigs[i]) * DD + d];
        sp += e2s[i] * val;
        ss += e1s[i] * val;
    }
    pP[i4][d] = sp; pS[i4][d] = ss;
    __syncthreads();

    if (tid < 64) {
        g_segP[(k * NSEG + seg) * DD + d] = pP[0][d] + pP[1][d] + pP[2][d] + pP[3][d];
        g_segS[(k * NSEG + seg) * DD + d] = pS[0][d] + pS[1][d] + pS[2][d] + pS[3][d];
    } else if (tid < 96) {
        int lane = tid - 64;
        float a = e2s[lane] + e2s[lane + 32];
        float b = e1s[lane] + e1s[lane + 32];
#pragma unroll
        for (int o = 16; o > 0; o >>= 1) {
            a += __shfl_down_sync(0xffffffffu, a, o);
            b += __shfl_down_sync(0xffffffffu, b, o);
        }
        if (lane == 0) {
            g_segPs[k * NSEG + seg] = a;
            g_segSs[k * NSEG + seg] = b;
        }
    }
}

// ============================================================================
// K3c: fill per-sublist cumsum tables. Offsets restricted to own sublist.
// ============================================================================
__global__ __launch_bounds__(256) void k_fill()
{
    const int seg = blockIdx.x, k = blockIdx.y;
    const int tid = threadIdx.x;
    const int s4 = tid >> 6, d = tid & 63;
    const int sub = seg >> 5;               // 32 segments per sublist
    const int subbase = sub << 5;
    const size_t basex = ((size_t)k * 2 + sub) * TBL;

    __shared__ float valP[64][64];
    __shared__ float valS[64][64];
    __shared__ float pP[4][64], pS[4][64];
    __shared__ float e1s[64], e2s[64];
    __shared__ float offPs_s, offSs_s;

    if (tid < 64) {
        int m = seg * SEG + tid;
        e1s[tid] = g_e1[k * NN + m];
        e2s[tid] = g_e2[k * NN + m];
    }

    float op = 0.f, os = 0.f;
    for (int s = s4; s < NSEG; s += 4) {
        float vP = g_segP[(k * NSEG + s) * DD + d];
        float vS = g_segS[(k * NSEG + s) * DD + d];
        if (s >= subbase && s < seg) op += vP;
        if (s > seg && s < subbase + 32) os += vS;
    }
    pP[s4][d] = op; pS[s4][d] = os;

#pragma unroll
    for (int it = 0; it < 16; it++) {
        int i = it * 4 + s4;
        int m = seg * SEG + i;
        float val = g_xt[((size_t)k * NN + g_sigma[k * NN + m]) * DD + d];
        valP[i][d] = g_e2[k * NN + m] * val;
        valS[i][d] = g_e1[k * NN + m] * val;
    }

    if (tid >= 224) {
        int lane = tid - 224;
        float a = 0.f, b = 0.f;
        for (int s = lane; s < NSEG; s += 32) {
            float vA = g_segPs[k * NSEG + s];
            float vB = g_segSs[k * NSEG + s];
            if (s >= subbase && s < seg) a += vA;
            if (s > seg && s < subbase + 32) b += vB;
        }
#pragma unroll
        for (int o = 16; o > 0; o >>= 1) {
            a += __shfl_down_sync(0xffffffffu, a, o);
            b += __shfl_down_sync(0xffffffffu, b, o);
        }
        if (lane == 0) { offPs_s = a; offSs_s = b; }
    }
    __syncthreads();

    const int mloc0 = (seg - subbase) * SEG;     // local position of segment start

    if (tid < 64) {
        float run = pP[0][d] + pP[1][d] + pP[2][d] + pP[3][d];
#pragma unroll 8
        for (int i = 0; i < SEG; i++) {
            run += valP[i][d];
            g_P2x[(basex + mloc0 + i + 1) * DD + d] = run;
        }
        if (seg == subbase) g_P2x[basex * DD + d] = 0.f;
    } else if (tid < 128) {
        int d2 = tid - 64;
        float runS = pS[0][d2] + pS[1][d2] + pS[2][d2] + pS[3][d2];
#pragma unroll 8
        for (int i = SEG - 1; i >= 0; i--) {
            runS += valS[i][d2];
            g_S1x[(basex + mloc0 + i) * DD + d2] = runS;
        }
        if (seg == subbase + 31) g_S1x[(basex + NS) * DD + d2] = 0.f;
    } else if (tid == 128) {
        float r = offPs_s;
        for (int i = 0; i < SEG; i++) {
            r += e2s[i];
            g_P2s[basex + mloc0 + i + 1] = r;
        }
        if (seg == subbase) g_P2s[basex] = 0.f;
    } else if (tid == 160) {
        float rS = offSs_s;
        for (int i = SEG - 1; i >= 0; i--) {
            rS += e1s[i];
            g_S1s[basex + mloc0 + i] = rS;
        }
        if (seg == subbase + 31) g_S1s[basex + NS] = 0.f;
    }
}

// ============================================================================
// K4: final output. Two parallel binary searches (one per sublist), sum both.
// ============================================================================
__global__ void k_out(float* __restrict__ out)
{
    const int n = blockIdx.x;
    const int k = threadIdx.x >> 6;
    const int d = threadIdx.x & 63;

    __shared__ int sj[KH][2];

    if (d < 2) {
        float a = g_ssrc[k * NN + n];
        float key = -a;
        const float* bs = &g_bsorted[k * NN + d * NS];
        int lo = 0, hi = NS;
        while (lo < hi) {
            int mid = (lo + hi) >> 1;
            if (bs[mid] < key) lo = mid + 1; else hi = mid;
        }
        sj[k][d] = lo;
    }
    __syncthreads();

    float a = g_ssrc[k * NN + n];
    float l1 = a + g_bmax[k];
    float t  = (l1 >= 0.f) ? l1 : 0.2f * l1;
    float w1 = expf(l1 - t);
    float w2 = expf(0.2f * l1 - t);

    size_t b0 = ((size_t)k * 2 + 0) * TBL + sj[k][0];
    size_t b1 = ((size_t)k * 2 + 1) * TBL + sj[k][1];
    float den = w1 * (g_S1s[b0] + g_S1s[b1]) + w2 * (g_P2s[b0] + g_P2s[b1]);
    float num = w1 * (g_S1x[b0 * DD + d] + g_S1x[b1 * DD + d])
              + w2 * (g_P2x[b0 * DD + d] + g_P2x[b1 * DD + d]);

    out[(size_t)n * (KH * DD) + k * DD + d] = tanhf(num / den);
}

// ============================================================================
extern "C" void kernel_launch(void* const* d_in, const int* in_sizes, int n_in,
                              void* d_out, int out_size)
{
    const float* prices = (const float*)d_in[0];
    const float* news   = (const float*)d_in[1];
    const float* Wbil   = (const float*)d_in[2];
    const float* bbil   = (const float*)d_in[3];
    const float* Wt     = (const float*)d_in[4];
    const float* avec   = (const float*)d_in[5];
    float* out = (float*)d_out;

    cudaFuncSetAttribute(k_wsplit, cudaFuncAttributeMaxDynamicSharedMemorySize, 66560);
    cudaFuncSetAttribute(k_bil_hmma, cudaFuncAttributeMaxDynamicSharedMemorySize, BIL_SMEM);

    // 4th launch (ncu capture slot) = k_sort
    k_wsplit<<<HD, 256, 66560>>>(Wbil);
    k_bil_hmma<<<dim3(NN / 128, HD / 8), 256, BIL_SMEM>>>(prices, news, bbil);
    k_xt<<<dim3(NN / 128, (KH * DD) / 128), 256>>>(Wt, avec);
    k_sort<<<dim3(2, KH), 1024>>>();
    k_segsum<<<dim3(NSEG, KH), 256>>>();
    k_fill<<<dim3(NSEG, KH), 256>>>();
    k_out<<<NN, KH * DD>>>(out);
}

// round 16
// speedup vs baseline: 1.0522x; 1.0522x over previous
#include <cuda_runtime.h>
#include <cuda_bf16.h>
#include <math.h>
#include <stdint.h>

// Problem constants
#define NN   4096
#define PP   128
#define QQ   128
#define HD   256
#define KH   8
#define DD   64
#define SEG  64
#define NSEG 64
#define NS   2048            // sublist length (2 sublists per head)
#define TBL  2049            // per-sublist table entries

// ======================= helpers =============================
__device__ __forceinline__ uint32_t smem_u32(const void* p) {
    uint32_t a;
    asm("{ .reg .u64 t; cvta.to.shared.u64 t, %1; cvt.u32.u64 %0, t; }" : "=r"(a) : "l"(p));
    return a;
}
__device__ __forceinline__ void cp16(uint32_t saddr, const void* g) {
    asm volatile("cp.async.cg.shared.global [%0], [%1], 16;" :: "r"(saddr), "l"(g) : "memory");
}
#define CP_COMMIT() asm volatile("cp.async.commit_group;" ::: "memory")
#define CP_WAIT(n)  asm volatile("cp.async.wait_group %0;" :: "n"(n) : "memory")

__device__ __forceinline__ void ldsm4(uint32_t* r, uint32_t addr) {
    asm volatile("ldmatrix.sync.aligned.m8n8.x4.shared.b16 {%0,%1,%2,%3}, [%4];"
        : "=r"(r[0]), "=r"(r[1]), "=r"(r[2]), "=r"(r[3]) : "r"(addr));
}
__device__ __forceinline__ void mma_bf16(float* c, const uint32_t* a, const uint32_t* b) {
    asm volatile("mma.sync.aligned.m16n8k16.row.col.f32.bf16.bf16.f32 "
        "{%0,%1,%2,%3}, {%4,%5,%6,%7}, {%8,%9}, {%0,%1,%2,%3};"
        : "+f"(c[0]), "+f"(c[1]), "+f"(c[2]), "+f"(c[3])
        : "r"(a[0]), "r"(a[1]), "r"(a[2]), "r"(a[3]), "r"(b[0]), "r"(b[1]));
}
__device__ __forceinline__ uint32_t pack2(__nv_bfloat16 a, __nv_bfloat16 b) {
    return (uint32_t)__bfloat16_as_ushort(a) | ((uint32_t)__bfloat16_as_ushort(b) << 16);
}

// ---------------- device scratch ----------------
__device__ __nv_bfloat16 g_Whi[HD * PP * QQ];    // [h][q][p] transposed, hi part
__device__ __nv_bfloat16 g_Wlo[HD * PP * QQ];    // lo part
__device__ float g_x[NN * HD];
__device__ float g_xt[KH * NN * DD];
__device__ float g_ssrc[KH * NN];
__device__ float g_sdst[KH * NN];
__device__ float g_bsorted[KH * NN];
__device__ int   g_sigma[KH * NN];
__device__ float g_e1[KH * NN];
__device__ float g_e2[KH * NN];
__device__ float g_bmax[KH];
__device__ unsigned int g_bmaxu[KH];
__device__ float g_segP[KH * NSEG * DD];
__device__ float g_segS[KH * NSEG * DD];
__device__ float g_segPs[KH * NSEG];
__device__ float g_segSs[KH * NSEG];
__device__ float g_P2x[KH * 2 * TBL * DD];       // per-sublist prefix of e2*xt
__device__ float g_S1x[KH * 2 * TBL * DD];       // per-sublist suffix of e1*xt
__device__ float g_P2s[KH * 2 * TBL];
__device__ float g_S1s[KH * 2 * TBL];

// ============================================================================
// K0: split W into bf16 hi/lo, transposed to [h][q][p]. Also zero g_bmaxu.
// ============================================================================
__global__ __launch_bounds__(256) void k_wsplit(const float* __restrict__ W)
{
    extern __shared__ float ws[];   // [128][130] fp32
    const int h = blockIdx.x;
    const int tid = threadIdx.x;

    if (blockIdx.x == 0 && tid < KH) g_bmaxu[tid] = 0u;

    for (int e = tid; e < PP * QQ; e += 256) {
        int p = e >> 7, q = e & 127;
        ws[p * 130 + q] = W[(size_t)h * PP * QQ + e];
    }
    __syncthreads();

    uint4* dhi = (uint4*)(g_Whi + (size_t)h * PP * QQ);
    uint4* dlo = (uint4*)(g_Wlo + (size_t)h * PP * QQ);
#pragma unroll
    for (int i = 0; i < 8; i++) {
        int o8 = tid + i * 256;
        int q  = o8 >> 4;
        int p0 = (o8 & 15) * 8;
        unsigned short hs[8], ls[8];
#pragma unroll
        for (int j = 0; j < 8; j++) {
            float x = ws[(p0 + j) * 130 + q];
            __nv_bfloat16 hb = __float2bfloat16(x);
            __nv_bfloat16 lb = __float2bfloat16(x - __bfloat162float(hb));
            hs[j] = __bfloat16_as_ushort(hb);
            ls[j] = __bfloat16_as_ushort(lb);
        }
        uint4 vh, vl;
        vh.x = hs[0] | ((uint32_t)hs[1] << 16); vh.y = hs[2] | ((uint32_t)hs[3] << 16);
        vh.z = hs[4] | ((uint32_t)hs[5] << 16); vh.w = hs[6] | ((uint32_t)hs[7] << 16);
        vl.x = ls[0] | ((uint32_t)ls[1] << 16); vl.y = ls[2] | ((uint32_t)ls[3] << 16);
        vl.z = ls[4] | ((uint32_t)ls[5] << 16); vl.w = ls[6] | ((uint32_t)ls[7] << 16);
        dhi[o8] = vh;
        dlo[o8] = vl;
    }
}

// ============================================================================
// K1: bilinear via HMMA (frozen R9 config). 261us proven.
// ============================================================================
#define ASTRIDE 272
#define A_HI    0
#define A_LO    34816
#define B_BASE  69632
#define B_STAGE 69632
#define B_LO_OFF 34816
#define SM_RED  208896
#define BIL_SMEM (208896 + 8192)

__device__ __forceinline__ void prefB(uint32_t dstbase, int h, int tid)
{
    const char* shi = (const char*)g_Whi + (size_t)h * 32768;
    const char* slo = (const char*)g_Wlo + (size_t)h * 32768;
#pragma unroll
    for (int i = 0; i < 8; i++) {
        int c = tid + i * 256;
        uint32_t d = dstbase + (uint32_t)(c >> 4) * ASTRIDE + (uint32_t)(c & 15) * 16;
        cp16(d, shi + (size_t)c * 16);
        cp16(d + B_LO_OFF, slo + (size_t)c * 16);
    }
}

__global__ __launch_bounds__(256, 1)
void k_bil_hmma(const float* __restrict__ prices,
                const float* __restrict__ news,
                const float* __restrict__ bias)
{
    extern __shared__ char sm[];
    const uint32_t sb = smem_u32(sm);
    float* red = (float*)(sm + SM_RED);     // [2][128][8]
    const int tid  = threadIdx.x;
    const int wid  = tid >> 5;
    const int lane = tid & 31;
    const int n0   = blockIdx.x * 128;
    const int h0   = blockIdx.y * 8;
    const int g = lane >> 2, ctg = lane & 3;
    const int wm = wid & 3;
    const int ch = wid >> 2;

    prefB(sb + B_BASE, h0, tid);
    CP_COMMIT();

#pragma unroll
    for (int i = 0; i < 16; i++) {
        int e4  = tid + i * 256;
        int row = e4 >> 5;
        int c4  = e4 & 31;
        float4 v = *(const float4*)&prices[(size_t)(n0 + row) * PP + c4 * 4];
        __nv_bfloat16 hx = __float2bfloat16(v.x), hy = __float2bfloat16(v.y);
        __nv_bfloat16 hz = __float2bfloat16(v.z), hw = __float2bfloat16(v.w);
        uint2 vh, vl;
        vh.x = pack2(hx, hy); vh.y = pack2(hz, hw);
        vl.x = pack2(__float2bfloat16(v.x - __bfloat162float(hx)),
                     __float2bfloat16(v.y - __bfloat162float(hy)));
        vl.y = pack2(__float2bfloat16(v.z - __bfloat162float(hz)),
                     __float2bfloat16(v.w - __bfloat162float(hw)));
        uint32_t off = (uint32_t)row * ASTRIDE + (uint32_t)c4 * 8;
        *(uint2*)(sm + A_HI + off) = vh;
        *(uint2*)(sm + A_LO + off) = vl;
    }

    const uint32_t arow = (uint32_t)(lane & 15);
    const uint32_t akb  = (uint32_t)(lane >> 4) * 16;
    const uint32_t ahi0 = sb + A_HI + (wm * 32 + arow) * ASTRIDE + akb;
    const uint32_t alo0 = ahi0 + (A_LO - A_HI);
    const uint32_t brow = (uint32_t)((lane & 7) + ((lane >> 4) << 3));
    const uint32_t bkb  = (uint32_t)((lane >> 3) & 1) * 16;
    const uint32_t boff = (ch * 64 + brow) * ASTRIDE + bkb;

#pragma unroll 1
    for (int hh = 0; hh < 8; hh++) {
        CP_WAIT(0);
        __syncthreads();

        if (hh > 0 && tid < 128) {
            const float* rr = red + ((hh - 1) & 1) * 1024 + tid * 8;
            float s = ((rr[0] + rr[1]) + (rr[2] + rr[3]))
                    + ((rr[4] + rr[5]) + (rr[6] + rr[7]));
            g_x[(size_t)(n0 + tid) * HD + (h0 + hh - 1)] = s + bias[h0 + hh - 1];
        }
        if (hh < 7) { prefB(sb + B_BASE + ((hh + 1) & 1) * B_STAGE, h0 + hh + 1, tid); CP_COMMIT(); }

        float acc[2][4][2][4];
#pragma unroll
        for (int mt = 0; mt < 2; mt++)
#pragma unroll
            for (int nb = 0; nb < 4; nb++)
#pragma unroll
                for (int t = 0; t < 2; t++)
#pragma unroll
                    for (int c = 0; c < 4; c++) acc[mt][nb][t][c] = 0.f;

        const uint32_t bb = sb + B_BASE + (uint32_t)(hh & 1) * B_STAGE + boff;

#pragma unroll
        for (int ks = 0; ks < 8; ks++) {
            uint32_t ah[2][4], al[2][4];
            ldsm4(ah[0], ahi0 + ks * 32);
            ldsm4(ah[1], ahi0 + 16 * ASTRIDE + ks * 32);
            ldsm4(al[0], alo0 + ks * 32);
            ldsm4(al[1], alo0 + 16 * ASTRIDE + ks * 32);
            uint32_t bh[4][4], bl[4][4];
#pragma unroll
            for (int nb = 0; nb < 4; nb++) {
                ldsm4(bh[nb], bb + (uint32_t)nb * (16 * ASTRIDE) + ks * 32);
                ldsm4(bl[nb], bb + B_LO_OFF + (uint32_t)nb * (16 * ASTRIDE) + ks * 32);
            }
#pragma unroll
            for (int nb = 0; nb < 4; nb++)
#pragma unroll
                for (int mt = 0; mt < 2; mt++) {
                    mma_bf16(acc[mt][nb][0], ah[mt], bh[nb] + 0);
                    mma_bf16(acc[mt][nb][1], ah[mt], bh[nb] + 2);
                }
#pragma unroll
            for (int nb = 0; nb < 4; nb++)
#pragma unroll
                for (int mt = 0; mt < 2; mt++) {
                    mma_bf16(acc[mt][nb][0], ah[mt], bl[nb] + 0);
                    mma_bf16(acc[mt][nb][1], ah[mt], bl[nb] + 2);
                }
#pragma unroll
            for (int nb = 0; nb < 4; nb++)
#pragma unroll
                for (int mt = 0; mt < 2; mt++) {
                    mma_bf16(acc[mt][nb][0], al[mt], bh[nb] + 0);
                    mma_bf16(acc[mt][nb][1], al[mt], bh[nb] + 2);
                }
        }

        float* redw = red + (hh & 1) * 1024;
#pragma unroll
        for (int mt = 0; mt < 2; mt++) {
            const int r0 = n0 + wm * 32 + mt * 16 + g;
            const int r1 = r0 + 8;
            float2 nv0[8], nv1[8];
#pragma unroll
            for (int i = 0; i < 8; i++) {
                int col = ch * 64 + (i >> 1) * 16 + (i & 1) * 8 + ctg * 2;
                nv0[i] = *(const float2*)&news[(size_t)r0 * QQ + col];
                nv1[i] = *(const float2*)&news[(size_t)r1 * QQ + col];
            }
            float xp0 = 0.f, xp1 = 0.f;
#pragma unroll
            for (int i = 0; i < 8; i++) {
                int nb = i >> 1, t = i & 1;
                xp0 += acc[mt][nb][t][0] * nv0[i].x + acc[mt][nb][t][1] * nv0[i].y;
                xp1 += acc[mt][nb][t][2] * nv1[i].x + acc[mt][nb][t][3] * nv1[i].y;
            }
            redw[(wm * 32 + mt * 16 + g) * 8 + ch * 4 + ctg]     = xp0;
            redw[(wm * 32 + mt * 16 + g + 8) * 8 + ch * 4 + ctg] = xp1;
        }
    }

    __syncthreads();
    if (tid < 128) {
        const float* rr = red + 1 * 1024 + tid * 8;
        float s = ((rr[0] + rr[1]) + (rr[2] + rr[3]))
                + ((rr[4] + rr[5]) + (rr[6] + rr[7]));
        g_x[(size_t)(n0 + tid) * HD + (h0 + 7)] = s + bias[h0 + 7];
    }
}

// ============================================================================
// K2: xt = x @ Wt^T -> g_xt; fused s_src/s_dst + warp-reduced bmax atomics.
// ============================================================================
__global__ __launch_bounds__(256, 2)
void k_xt(const float* __restrict__ Wt, const float* __restrict__ avec)
{
    const int n0 = blockIdx.x * 128;
    const int j0 = blockIdx.y * 128;
    const int tid = threadIdx.x;
    const int tx = tid & 15;
    const int ty = tid >> 4;

    __shared__ float As[16][128];
    __shared__ float Bs[16][128];
    __shared__ float sredS[2][128][8];
    __shared__ float sredD[2][128][8];

    float acc[8][8];
#pragma unroll
    for (int i = 0; i < 8; i++)
#pragma unroll
        for (int j = 0; j < 8; j++) acc[i][j] = 0.f;

    for (int h0 = 0; h0 < HD; h0 += 16) {
#pragma unroll
        for (int l = 0; l < 2; l++) {
            int f = tid + l * 256;
            int n = f >> 2;
            int hv = (f & 3) * 4;
            float4 v = *(const float4*)&g_x[(size_t)(n0 + n) * HD + h0 + hv];
            As[hv + 0][n] = v.x; As[hv + 1][n] = v.y;
            As[hv + 2][n] = v.z; As[hv + 3][n] = v.w;
        }
#pragma unroll
        for (int l = 0; l < 2; l++) {
            int f = tid + l * 256;
            int j = f >> 2;
            int hv = (f & 3) * 4;
            float4 v = *(const float4*)&Wt[(size_t)(j0 + j) * HD + h0 + hv];
            Bs[hv + 0][j] = v.x; Bs[hv + 1][j] = v.y;
            Bs[hv + 2][j] = v.z; Bs[hv + 3][j] = v.w;
        }
        __syncthreads();
#pragma unroll
        for (int kk = 0; kk < 16; kk++) {
            float a[8], b[8];
            *(float4*)&a[0] = *(const float4*)&As[kk][ty * 8];
            *(float4*)&a[4] = *(const float4*)&As[kk][ty * 8 + 4];
            *(float4*)&b[0] = *(const float4*)&Bs[kk][tx * 8];
            *(float4*)&b[4] = *(const float4*)&Bs[kk][tx * 8 + 4];
#pragma unroll
            for (int i = 0; i < 8; i++)
#pragma unroll
                for (int j = 0; j < 8; j++) acc[i][j] += a[i] * b[j];
        }
        __syncthreads();
    }

#pragma unroll
    for (int i = 0; i < 8; i++) {
        int n = n0 + ty * 8 + i;
#pragma unroll
        for (int jj = 0; jj < 8; jj++) {
            int j = j0 + tx * 8 + jj;
            int k = j >> 6, d = j & 63;
            g_xt[((size_t)k * NN + n) * DD + d] = acc[i][jj];
        }
    }

    // fused scores
    {
        const int khalf = tx >> 3;
        const int kk = (j0 >> 6) + khalf;
        const float* av = avec + kk * 128 + (tx & 7) * 8;
        float asv[8], adv[8];
#pragma unroll
        for (int jj = 0; jj < 8; jj++) { asv[jj] = av[jj]; adv[jj] = av[64 + jj]; }
#pragma unroll
        for (int i = 0; i < 8; i++) {
            float ps = 0.f, pd = 0.f;
#pragma unroll
            for (int jj = 0; jj < 8; jj++) {
                ps += acc[i][jj] * asv[jj];
                pd += acc[i][jj] * adv[jj];
            }
            sredS[khalf][ty * 8 + i][tx & 7] = ps;
            sredD[khalf][ty * 8 + i][tx & 7] = pd;
        }
    }
    __syncthreads();
    {
        const int khalf = tid >> 7;
        const int n = tid & 127;
        const int kk = (j0 >> 6) + khalf;
        const float* rs = sredS[khalf][n];
        const float* rd = sredD[khalf][n];
        float ss = ((rs[0] + rs[1]) + (rs[2] + rs[3])) + ((rs[4] + rs[5]) + (rs[6] + rs[7]));
        float sd = ((rd[0] + rd[1]) + (rd[2] + rd[3])) + ((rd[4] + rd[5]) + (rd[6] + rd[7]));
        g_ssrc[kk * NN + n0 + n] = ss;
        g_sdst[kk * NN + n0 + n] = sd;
        // warp-pre-reduced max, then one atomic per warp (same kk per warp)
        uint32_t u = __float_as_uint(sd);
        uint32_t enc = (u & 0x80000000u) ? ~u : (u | 0x80000000u);
#pragma unroll
        for (int o = 16; o > 0; o >>= 1) {
            uint32_t other = __shfl_xor_sync(0xffffffffu, enc, o);
            if (other > enc) enc = other;
        }
        if ((tid & 31) == 0) atomicMax(&g_bmaxu[kk], enc);
    }
}

// ============================================================================
// K3a: bitonic sort of independent 2048-sublists. grid (2, KH), 1024 threads.
// u32 keys (top-20 monotone bits | 12-bit local idx). bmax from g_bmaxu.
// ============================================================================
__global__ __launch_bounds__(1024)
void k_sort()
{
    const int sub = blockIdx.x;
    const int k = blockIdx.y;
    const int base = k * NN + sub * NS;
    __shared__ uint32_t v[NS];   // 8KB

    for (int i = threadIdx.x; i < NS; i += 1024) {
        uint32_t u = __float_as_uint(g_sdst[base + i]);
        uint32_t key = (u & 0x80000000u) ? ~u : (u | 0x80000000u);
        v[i] = (key & 0xFFFFF000u) | (uint32_t)i;
    }

    int prev = 64;
    for (int size = 2; size <= NS; size <<= 1) {
        for (int stride = size >> 1; stride > 0; stride >>= 1) {
            if (prev > 32 || stride > 32) __syncthreads(); else __syncwarp();
            int t = threadIdx.x;                 // exactly NS/2 = 1024 pairs
            int i = (t << 1) - (t & (stride - 1));
            int j = i + stride;
            bool up = ((i & size) == 0);
            uint32_t a = v[i], b = v[j];
            if ((a > b) == up) { v[i] = b; v[j] = a; }
            prev = stride;
        }
    }
    __syncthreads();

    uint32_t e = g_bmaxu[k];
    uint32_t um = (e & 0x80000000u) ? (e ^ 0x80000000u) : ~e;
    const float bmax = __uint_as_float(um);

    for (int i = threadIdx.x; i < NS; i += 1024) {
        int idx = (int)(v[i] & 0xFFFu);
        float val = g_sdst[base + idx];
        g_bsorted[base + i] = val;
        g_sigma[base + i]   = sub * NS + idx;
        float b = val - bmax;
        g_e1[base + i] = expf(b);
        g_e2[base + i] = expf(0.2f * b);
    }
    if (threadIdx.x == 0 && sub == 0) g_bmax[k] = bmax;
}

// ============================================================================
// K3b: per-segment sums
// ============================================================================
__global__ __launch_bounds__(256) void k_segsum()
{
    const int seg = blockIdx.x, k = blockIdx.y;
    const int tid = threadIdx.x;
    const int i4 = tid >> 6, d = tid & 63;

    __shared__ float e1s[64], e2s[64];
    __shared__ int   sigs[64];
    __shared__ float pP[4][64], pS[4][64];

    if (tid < 64) {
        int m = seg * SEG + tid;
        e1s[tid] = g_e1[k * NN + m];
        e2s[tid] = g_e2[k * NN + m];
        sigs[tid] = g_sigma[k * NN + m];
    }
    __syncthreads();

    float sp = 0.f, ss = 0.f;
#pragma unroll
    for (int it = 0; it < 16; it++) {
        int i = it * 4 + i4;
        float val = g_xt[((size_t)k * NN + sigs[i]) * DD + d];
        sp += e2s[i] * val;
        ss += e1s[i] * val;
    }
    pP[i4][d] = sp; pS[i4][d] = ss;
    __syncthreads();

    if (tid < 64) {
        g_segP[(k * NSEG + seg) * DD + d] = pP[0][d] + pP[1][d] + pP[2][d] + pP[3][d];
        g_segS[(k * NSEG + seg) * DD + d] = pS[0][d] + pS[1][d] + pS[2][d] + pS[3][d];
    } else if (tid < 96) {
        int lane = tid - 64;
        float a = e2s[lane] + e2s[lane + 32];
        float b = e1s[lane] + e1s[lane + 32];
#pragma unroll
        for (int o = 16; o > 0; o >>= 1) {
            a += __shfl_down_sync(0xffffffffu, a, o);
            b += __shfl_down_sync(0xffffffffu, b, o);
        }
        if (lane == 0) {
            g_segPs[k * NSEG + seg] = a;
            g_segSs[k * NSEG + seg] = b;
        }
    }
}

// ============================================================================
// K3c: fill per-sublist cumsum tables. Offsets restricted to own sublist.
// ============================================================================
__global__ __launch_bounds__(256) void k_fill()
{
    const int seg = blockIdx.x, k = blockIdx.y;
    const int tid = threadIdx.x;
    const int s4 = tid >> 6, d = tid & 63;
    const int sub = seg >> 5;
    const int subbase = sub << 5;
    const size_t basex = ((size_t)k * 2 + sub) * TBL;

    __shared__ float valP[64][64];
    __shared__ float valS[64][64];
    __shared__ float pP[4][64], pS[4][64];
    __shared__ float e1s[64], e2s[64];
    __shared__ float offPs_s, offSs_s;

    if (tid < 64) {
        int m = seg * SEG + tid;
        e1s[tid] = g_e1[k * NN + m];
        e2s[tid] = g_e2[k * NN + m];
    }

    float op = 0.f, os = 0.f;
    for (int s = s4; s < NSEG; s += 4) {
        float vP = g_segP[(k * NSEG + s) * DD + d];
        float vS = g_segS[(k * NSEG + s) * DD + d];
        if (s >= subbase && s < seg) op += vP;
        if (s > seg && s < subbase + 32) os += vS;
    }
    pP[s4][d] = op; pS[s4][d] = os;

#pragma unroll
    for (int it = 0; it < 16; it++) {
        int i = it * 4 + s4;
        int m = seg * SEG + i;
        float val = g_xt[((size_t)k * NN + g_sigma[k * NN + m]) * DD + d];
        valP[i][d] = g_e2[k * NN + m] * val;
        valS[i][d] = g_e1[k * NN + m] * val;
    }

    if (tid >= 224) {
        int lane = tid - 224;
        float a = 0.f, b = 0.f;
        for (int s = lane; s < NSEG; s += 32) {
            float vA = g_segPs[k * NSEG + s];
            float vB = g_segSs[k * NSEG + s];
            if (s >= subbase && s < seg) a += vA;
            if (s > seg && s < subbase + 32) b += vB;
        }
#pragma unroll
        for (int o = 16; o > 0; o >>= 1) {
            a += __shfl_down_sync(0xffffffffu, a, o);
            b += __shfl_down_sync(0xffffffffu, b, o);
        }
        if (lane == 0) { offPs_s = a; offSs_s = b; }
    }
    __syncthreads();

    const int mloc0 = (seg - subbase) * SEG;

    if (tid < 64) {
        float run = pP[0][d] + pP[1][d] + pP[2][d] + pP[3][d];
#pragma unroll 8
        for (int i = 0; i < SEG; i++) {
            run += valP[i][d];
            g_P2x[(basex + mloc0 + i + 1) * DD + d] = run;
        }
        if (seg == subbase) g_P2x[basex * DD + d] = 0.f;
    } else if (tid < 128) {
        int d2 = tid - 64;
        float runS = pS[0][d2] + pS[1][d2] + pS[2][d2] + pS[3][d2];
#pragma unroll 8
        for (int i = SEG - 1; i >= 0; i--) {
            runS += valS[i][d2];
            g_S1x[(basex + mloc0 + i) * DD + d2] = runS;
        }
        if (seg == subbase + 31) g_S1x[(basex + NS) * DD + d2] = 0.f;
    } else if (tid == 128) {
        float r = offPs_s;
        for (int i = 0; i < SEG; i++) {
            r += e2s[i];
            g_P2s[basex + mloc0 + i + 1] = r;
        }
        if (seg == subbase) g_P2s[basex] = 0.f;
    } else if (tid == 160) {
        float rS = offSs_s;
        for (int i = SEG - 1; i >= 0; i--) {
            rS += e1s[i];
            g_S1s[basex + mloc0 + i] = rS;
        }
        if (seg == subbase + 31) g_S1s[basex + NS] = 0.f;
    }
}

// ============================================================================
// K4: final output. Two parallel binary searches (one per sublist), sum both.
// ============================================================================
__global__ void k_out(float* __restrict__ out)
{
    const int n = blockIdx.x;
    const int k = threadIdx.x >> 6;
    const int d = threadIdx.x & 63;

    __shared__ int sj[KH][2];

    if (d < 2) {
        float a = g_ssrc[k * NN + n];
        float key = -a;
        const float* bs = &g_bsorted[k * NN + d * NS];
        int lo = 0, hi = NS;
        while (lo < hi) {
            int mid = (lo + hi) >> 1;
            if (bs[mid] < key) lo = mid + 1; else hi = mid;
        }
        sj[k][d] = lo;
    }
    __syncthreads();

    float a = g_ssrc[k * NN + n];
    float l1 = a + g_bmax[k];
    float t  = (l1 >= 0.f) ? l1 : 0.2f * l1;
    float w1 = expf(l1 - t);
    float w2 = expf(0.2f * l1 - t);

    size_t b0 = ((size_t)k * 2 + 0) * TBL + sj[k][0];
    size_t b1 = ((size_t)k * 2 + 1) * TBL + sj[k][1];
    float den = w1 * (g_S1s[b0] + g_S1s[b1]) + w2 * (g_P2s[b0] + g_P2s[b1]);
    float num = w1 * (g_S1x[b0 * DD + d] + g_S1x[b1 * DD + d])
              + w2 * (g_P2x[b0 * DD + d] + g_P2x[b1 * DD + d]);

    out[(size_t)n * (KH * DD) + k * DD + d] = tanhf(num / den);
}

// ============================================================================
extern "C" void kernel_launch(void* const* d_in, const int* in_sizes, int n_in,
                              void* d_out, int out_size)
{
    const float* prices = (const float*)d_in[0];
    const float* news   = (const float*)d_in[1];
    const float* Wbil   = (const float*)d_in[2];
    const float* bbil   = (const float*)d_in[3];
    const float* Wt     = (const float*)d_in[4];
    const float* avec   = (const float*)d_in[5];
    float* out = (float*)d_out;

    cudaFuncSetAttribute(k_wsplit, cudaFuncAttributeMaxDynamicSharedMemorySize, 66560);
    cudaFuncSetAttribute(k_bil_hmma, cudaFuncAttributeMaxDynamicSharedMemorySize, BIL_SMEM);

    // 4th launch (ncu capture slot) = k_sort
    k_wsplit<<<HD, 256, 66560>>>(Wbil);
    k_bil_hmma<<<dim3(NN / 128, HD / 8), 256, BIL_SMEM>>>(prices, news, bbil);
    k_xt<<<dim3(NN / 128, (KH * DD) / 128), 256>>>(Wt, avec);
    k_sort<<<dim3(2, KH), 1024>>>();
    k_segsum<<<dim3(NSEG, KH), 256>>>();
    k_fill<<<dim3(NSEG, KH), 256>>>();
    k_out<<<NN, KH * DD>>>(out);
}